// round 17
// baseline (speedup 1.0000x reference)
#include <cuda_runtime.h>
#include <cstdint>

#define PI_F 3.14159265358979323846f

// Packed 4-bit species table (up to 131072 atoms)
__device__ __align__(16) unsigned g_pk[16384];

// ---------------------------------------------------------------------------
// Prep kernel: zero aev AND pack atomic_numbers into 4-bit nibbles.
// (Combined kernel proven cheaper than memset-node + pack kernel.)
// ---------------------------------------------------------------------------
__global__ void ani_prep_kernel(const int* __restrict__ an, int N, int PKW,
                                float4* __restrict__ aevv, long long aev_v4)
{
    long long t = (long long)blockIdx.x * blockDim.x + threadIdx.x;
    const float4 z = make_float4(0.f, 0.f, 0.f, 0.f);
    for (long long v = t; v < aev_v4; v += (long long)gridDim.x * blockDim.x)
        aevv[v] = z;
    if (t < PKW) {
        int base = (int)t << 3;
        unsigned v = 0;
#pragma unroll
        for (int k = 0; k < 8; k++) {
            int a = base + k;
            unsigned s = (a < N) ? (unsigned)an[a] : 0u;
            v |= (s & 15u) << (k * 4);
        }
        g_pk[t] = v;
    }
}

__device__ __forceinline__ float4 radial_half4(float d, float base_k, float fc)
{
    float a0 = d - base_k;
    float a1 = d - (base_k + 0.5375f);
    float a2 = d - (base_k + 1.075f);
    float a3 = d - (base_k + 1.6125f);
    return make_float4(0.25f * __expf(-19.7f * a0 * a0) * fc,
                       0.25f * __expf(-19.7f * a1 * a1) * fc,
                       0.25f * __expf(-19.7f * a2 * a2) * fc,
                       0.25f * __expf(-19.7f * a3 * a3) * fc);
}

// ---------------------------------------------------------------------------
// Fused kernel, 512 threads/block, 4 blocks/SM (100% occ), TWO 512-tiles
// per block (halves table bulk-copy traffic and per-block fixed costs):
//   smem = 25KB species table (cp.async.bulk) + 18.4KB stage (128 rows).
//   Angular flush = coalesced __stcs float4 (proven optimal structure).
//   Radial: Gaussian-window culling |d - mu_k| < 1.10 shells.
// ---------------------------------------------------------------------------
__global__ __launch_bounds__(512, 4)
void ani_fused_kernel(const float* __restrict__ r_ij,
                      const int*   __restrict__ pidx,
                      const int*   __restrict__ an,
                      const float* __restrict__ vec12,
                      float*       __restrict__ aev,
                      float*       __restrict__ ang,
                      int P, int T, int PKB /*bulk bytes, 0 = no table*/)
{
    __shared__ __align__(128) unsigned spk[6272];      // 25088B table
    __shared__ __align__(16)  float    sf[128 * 36];   // 18432B stage (128 rows)
    __shared__ __align__(8)   unsigned long long mbar;

    const int tid = threadIdx.x;
    const int b   = blockIdx.x;
    const bool use_table = (PKB > 0);

    uint32_t mbar_a = (uint32_t)__cvta_generic_to_shared(&mbar);

    if (use_table) {
        if (tid == 0) {
            asm volatile("mbarrier.init.shared.b64 [%0], 1;" :: "r"(mbar_a) : "memory");
            asm volatile("fence.proxy.async.shared::cta;" ::: "memory");
        }
        __syncthreads();
        if (tid == 0) {
            uint32_t dst = (uint32_t)__cvta_generic_to_shared(spk);
            asm volatile("mbarrier.arrive.expect_tx.shared.b64 _, [%0], %1;"
                         :: "r"(mbar_a), "r"((unsigned)PKB) : "memory");
            asm volatile("cp.async.bulk.shared::cluster.global.mbarrier::complete_tx::bytes "
                         "[%0], [%1], %2, [%3];"
                         :: "r"(dst), "l"((const void*)g_pk), "r"((unsigned)PKB), "r"(mbar_a)
                         : "memory");
        }
    }

    const float CZ[4] = { 0.9238795325f,  0.3826834324f, -0.3826834324f, -0.9238795325f };
    const float SZ[4] = { 0.3826834324f,  0.9238795325f,  0.9238795325f,  0.3826834324f };
    const long long limit = (long long)T * 32;

    // ==================== ANGULAR: two 512-tiles ==========================
#pragma unroll 1
    for (int sub = 0; sub < 2; sub++) {
        const long long tile = 2LL * b + sub;
        const long long t    = tile * 512 + tid;
        const bool vt = (t < T);

        float cost = 0.f, sint = 0.f, fc2x = 0.f;
        float frad[8];
#pragma unroll
        for (int a = 0; a < 8; a++) frad[a] = 0.f;

        if (vt) {
            const float* v1 = vec12 + 3LL * t;
            const float* v2 = vec12 + 3LL * T + 3LL * t;
            float x1 = __ldcs(v1 + 0), y1 = __ldcs(v1 + 1), z1 = __ldcs(v1 + 2);
            float x2 = __ldcs(v2 + 0), y2 = __ldcs(v2 + 1), z2 = __ldcs(v2 + 2);

            float d11 = fmaf(x1, x1, fmaf(y1, y1, z1 * z1));
            float d22 = fmaf(x2, x2, fmaf(y2, y2, z2 * z2));
            float d12 = fmaf(x1, x2, fmaf(y1, y2, z1 * z2));

            float rs1 = rsqrtf(d11);
            float rs2 = rsqrtf(d22);
            float d1  = d11 * rs1;
            float d2  = d22 * rs2;

            cost = 0.95f * d12 * rs1 * rs2;                 // |cost| <= 0.95
            sint = sqrtf(fmaxf(1.0f - cost * cost, 0.0f));  // theta in [0,pi]

            float fc1 = (d1 <= 3.5f) ? (0.5f * __cosf((PI_F / 3.5f) * d1) + 0.5f) : 0.0f;
            float fc2 = (d2 <= 3.5f) ? (0.5f * __cosf((PI_F / 3.5f) * d2) + 0.5f) : 0.0f;
            fc2x = 2.0f * fc1 * fc2;

            float u = 0.5f * (d1 + d2);
#pragma unroll
            for (int a = 0; a < 8; a++) {
                float dd = u - (0.8f + 0.3375f * (float)a);   // ShfA[a]
                frad[a] = __expf(-12.5f * dd * dd);
            }
        }

        // 4 staging passes: outputs generated inside the pass
#pragma unroll
        for (int pass = 0; pass < 4; pass++) {
            if ((tid >> 7) == pass) {
                int r = tid & 127;
#pragma unroll
                for (int z = 0; z < 4; z++) {
                    float xz = 0.5f * (1.0f + cost * CZ[z] + sint * SZ[z]);   // in [0,1]
                    float fang = (xz > 0.0f) ? __powf(xz, 14.1f) : 0.0f;
                    fang *= fc2x;
                    float4 a0 = make_float4(fang * frad[0], fang * frad[1],
                                            fang * frad[2], fang * frad[3]);
                    float4 a1 = make_float4(fang * frad[4], fang * frad[5],
                                            fang * frad[6], fang * frad[7]);
                    *reinterpret_cast<float4*>(&sf[r * 36 + z * 8])     = a0;
                    *reinterpret_cast<float4*>(&sf[r * 36 + z * 8 + 4]) = a1;
                }
            }
            __syncthreads();

            // flush: all 512 threads, fully coalesced float4, evict-first
            const long long base = (tile * 512 + pass * 128) * 32;
            if (base < limit) {
                float4* outv = reinterpret_cast<float4*>(ang + base);
#pragma unroll
                for (int it = 0; it < 2; it++) {
                    int jj = tid + it * 512;
                    if (base + (long long)jj * 4 < limit) {
                        int qr = jj >> 3;
                        int k  = (jj & 7) << 2;
                        __stcs(&outv[jj], *reinterpret_cast<const float4*>(&sf[qr * 36 + k]));
                    }
                }
            }
            __syncthreads();
        }
    }

    // ---------------------- wait for species table ------------------------
    if (use_table) {
        unsigned done;
        do {
            asm volatile("{\n\t.reg .pred p;\n\t"
                         "mbarrier.try_wait.parity.shared.b64 p, [%1], 0;\n\t"
                         "selp.b32 %0, 1, 0, p;\n\t}"
                         : "=r"(done) : "r"(mbar_a) : "memory");
        } while (!done);
    }

    // ============ RADIAL: two 512-tiles (Gaussian-window culled) ==========
#pragma unroll 1
    for (int sub = 0; sub < 2; sub++) {
        const int q = (2 * b + sub) * 512 + tid;
        if (q < P) {
            float d = __ldcs(r_ij + q);
            int  ri = pidx[q];
            int  rj = pidx[P + q];
            int si, sj;
            if (use_table) {
                si = (spk[ri >> 3] >> ((ri & 7) * 4)) & 7;
                sj = (spk[rj >> 3] >> ((rj & 7) * 4)) & 7;
            } else {
                si = an[ri];
                sj = an[rj];
            }
            float fc = (d <= 5.1f) ? (0.5f * __cosf((PI_F / 5.1f) * d) + 0.5f) : 0.0f;

            // significant shells: |d - mu_k| < 1.10 shell units (0.59A)
            float s = (d - 0.8f) * 1.8604651f;            // 1/0.5375
            int klo = (int)ceilf(s - 1.10f);
            int khi = (int)floorf(s + 1.10f);
            klo = (klo < 0) ? 0 : ((klo > 7) ? 7 : klo);
            khi = (khi > 7) ? 7 : ((khi < 0) ? 0 : khi);
            int hlo = klo >> 2;
            int hhi = khi >> 2;

            float* rowA = aev + (long long)(ri * 7 + sj) * 8;
            float* rowB = aev + (long long)(rj * 7 + si) * 8;

            for (int h = hlo; h <= hhi; h++) {
                float4 g = radial_half4(d, 0.8f + 2.15f * (float)h, fc);
                atomicAdd(reinterpret_cast<float4*>(rowA + 4 * h), g);
                atomicAdd(reinterpret_cast<float4*>(rowB + 4 * h), g);
            }
        }
    }
}

// ---------------------------------------------------------------------------
// Inputs (metadata order): r_ij f32[P], pair_indices i32[2,P],
// atomic_numbers i32[N_ATOMS], vec12 f32[2,T,3].
// Output: aev f32[N_ATOMS*7, 8] followed by ang f32[T, 32].
// ---------------------------------------------------------------------------
extern "C" void kernel_launch(void* const* d_in, const int* in_sizes, int n_in,
                              void* d_out, int out_size)
{
    const float* r_ij  = (const float*)d_in[0];
    const int*   pidx  = (const int*)  d_in[1];
    const int*   an    = (const int*)  d_in[2];
    const float* vec12 = (const float*)d_in[3];

    const int P = in_sizes[0];
    const int T = in_sizes[3] / 6;
    const int N = in_sizes[2];
    const long long aev_elems = (long long)N * 7 * 8;

    float* aev = (float*)d_out;
    float* ang = aev + aev_elems;

    const int PKW = (N + 7) / 8;                      // packed words
    int PKB = ((PKW * 4) + 15) & ~15;                 // bulk bytes (16B multiple)
    if (PKB > 25088) PKB = 0;                         // table too big -> global gathers

    const int A5 = (T + 511) / 512;                   // angular tiles of 512
    const int R5 = (P + 511) / 512;                   // radial tiles of 512
    const int Tiles = (A5 > R5) ? A5 : R5;
    const int G = (Tiles + 1) / 2;                    // two tiles per block

    // zero aev + pack species in one kernel (proven cheapest prep)
    ani_prep_kernel<<<2048, 256>>>(an, N, (PKB > 0) ? (PKB / 4) : 0,
                                   (float4*)aev, aev_elems / 4);

    ani_fused_kernel<<<G, 512>>>(r_ij, pidx, an, vec12, aev, ang, P, T, PKB);
}